// round 5
// baseline (speedup 1.0000x reference)
#include <cuda_runtime.h>

typedef unsigned long long u64;

#define B_   256
#define T_   2048
#define DIN  64
#define H_   32
#define C_   16
#define R_   (B_ * T_)

// Scratch (allocation-free rule: __device__ globals)
__device__ float g_u[(size_t)R_ * H_];    // x@W_in^T + b_in + b_res_enc
__device__ float g_dec[(size_t)R_ * H_];  // decoder hidden states

#define FENCE() asm volatile("" ::: "memory")

// ---------------- packed f32x2 helpers (Blackwell FFMA2) ----------------
__device__ __forceinline__ u64 fma2(u64 a, u64 b, u64 c) {
    u64 d;
    asm("fma.rn.f32x2 %0, %1, %2, %3;" : "=l"(d) : "l"(a), "l"(b), "l"(c));
    return d;
}
__device__ __forceinline__ u64 add2(u64 a, u64 b) {
    u64 d;
    asm("add.rn.f32x2 %0, %1, %2;" : "=l"(d) : "l"(a), "l"(b));
    return d;
}
__device__ __forceinline__ u64 pack2(float lo, float hi) {
    u64 r;
    asm("mov.b64 %0, {%1, %2};" : "=l"(r) : "f"(lo), "f"(hi));
    return r;
}
__device__ __forceinline__ float unpack_sum(u64 v) {
    float lo, hi;
    asm("mov.b64 {%0, %1}, %2;" : "=f"(lo), "=f"(hi) : "l"(v));
    return lo + hi;
}
__device__ __forceinline__ float hsum4(u64 a0, u64 a1, u64 a2, u64 a3) {
    return unpack_sum(add2(add2(a0, a1), add2(a2, a3)));
}
// tanh = 1 - 2/(1+e^{2x}); e^{2x}: 0 -> -1, inf -> +1, no NaN path, no clamps
__device__ __forceinline__ float tanh_fast(float x) {
    float e = __expf(2.0f * x);
    return 1.0f - __fdividef(2.0f, 1.0f + e);
}

// ---------------- Kernel 1: u = x @ W_in^T + (b_in + b_res_enc) ----------------
// No smem. lane = h. x row broadcast via uniform-address LDG.128 (1 l1tex
// wavefront each, LSU-floor bound), W_in row held in registers. 2 rows/iter.
#define K1_GRID 304
__global__ void __launch_bounds__(128) k_proj_in(const float* __restrict__ x,
                                                 const float* __restrict__ Win,
                                                 const float* __restrict__ bin,
                                                 const float* __restrict__ brese) {
    const int lane = threadIdx.x & 31;
    const int gw   = (blockIdx.x * blockDim.x + threadIdx.x) >> 5;  // global warp
    const int nw   = (K1_GRID * 128) >> 5;                          // 1216 warps

    u64 Wr[DIN / 2];
    const u64* wrow = reinterpret_cast<const u64*>(Win + lane * DIN);
#pragma unroll
    for (int k = 0; k < DIN / 2; k++) Wr[k] = wrow[k];
    const float bias = bin[lane] + brese[lane];

    for (size_t r = (size_t)gw * 2; r < R_; r += (size_t)nw * 2) {
        const ulonglong2* p0 = reinterpret_cast<const ulonglong2*>(x + r * DIN);
        const ulonglong2* p1 = p0 + (DIN / 4);
        ulonglong2 X0[16], X1[16];
#pragma unroll
        for (int k = 0; k < 16; k++) X0[k] = __ldg(p0 + k);
#pragma unroll
        for (int k = 0; k < 16; k++) X1[k] = __ldg(p1 + k);

        u64 a0 = 0, a1 = 0, a2 = 0, a3 = 0;
#pragma unroll
        for (int k = 0; k < 16; k += 2) {
            a0 = fma2(Wr[2 * k],     X0[k].x,     a0);
            a1 = fma2(Wr[2 * k + 1], X0[k].y,     a1);
            a2 = fma2(Wr[2 * k + 2], X0[k + 1].x, a2);
            a3 = fma2(Wr[2 * k + 3], X0[k + 1].y, a3);
        }
        g_u[r * H_ + lane] = bias + hsum4(a0, a1, a2, a3);

        u64 b0 = 0, b1 = 0, b2 = 0, b3 = 0;
#pragma unroll
        for (int k = 0; k < 16; k += 2) {
            b0 = fma2(Wr[2 * k],     X1[k].x,     b0);
            b1 = fma2(Wr[2 * k + 1], X1[k].y,     b1);
            b2 = fma2(Wr[2 * k + 2], X1[k + 1].x, b2);
            b3 = fma2(Wr[2 * k + 3], X1[k + 1].y, b3);
        }
        g_u[(r + 1) * H_ + lane] = bias + hsum4(b0, b1, b2, b3);
    }
}

// ---------------- Kernel 2: 2-warp pipelined dual ESN scan ----------------
// warp0 (producer): h_enc recurrence + v = (W_co@W_code) h_enc  -> smem ring
// warp1 (consumer): h_dec = tanh(v + W_dec h_dec + btot)        -> g_dec
// Handoff: 32-step ring, batch-4 flags (volatile smem), per-SMSP in-order
// store commit gives data-before-flag ordering.
#define RINGD 32
__global__ void __launch_bounds__(64) k_scan(const float* __restrict__ Wenc_g,
                                             const float* __restrict__ Wdec_g,
                                             const float* __restrict__ Wcode,
                                             const float* __restrict__ bcode,
                                             const float* __restrict__ Wco,
                                             const float* __restrict__ bco,
                                             const float* __restrict__ bresd) {
    const int lane = threadIdx.x & 31;
    const int wid  = threadIdx.x >> 5;
    const int b    = blockIdx.x;
    __shared__ __align__(16) float ring[RINGD][H_];
    __shared__ __align__(16) float she[H_];
    __shared__ __align__(16) float shd[H_];
    __shared__ int enc_flag;   // steps completed by producer
    __shared__ int dec_flag;   // steps completed by consumer

    if (threadIdx.x == 0) { enc_flag = 0; dec_flag = 0; }
    __syncthreads();

    if (wid == 0) {
        // ---------------- producer: encoder + fused code->co projection ----
        u64 We[16], Mm[16];
        {
            const u64* a = reinterpret_cast<const u64*>(Wenc_g + lane * H_);
#pragma unroll
            for (int k = 0; k < 16; k++) We[k] = a[k];
        }
        {
            float wc[C_];
#pragma unroll
            for (int c = 0; c < C_; c++) wc[c] = Wco[lane * C_ + c];
#pragma unroll
            for (int k = 0; k < 16; k++) {
                u64 m = 0;
#pragma unroll
                for (int c = 0; c < C_; c++) {
                    m = fma2(pack2(wc[c], wc[c]),
                             reinterpret_cast<const u64*>(Wcode + c * H_)[k], m);
                }
                Mm[k] = m;
            }
        }
        u64 he[16];
#pragma unroll
        for (int k = 0; k < 16; k++) he[k] = 0ull;

        const float* up = g_u + ((size_t)b * T_) * H_ + lane;
        float ur[4];
#pragma unroll
        for (int i = 0; i < 4; i++) ur[i] = up[(size_t)i * H_];

        for (int t = 0; t < T_; t += 4) {
            // backpressure: don't run more than 24 steps ahead of consumer
            while (t - *(volatile int*)&dec_flag > 24) {}
#pragma unroll
            for (int i = 0; i < 4; i++) {
                const float u = ur[i];
                const int tn  = t + 4 + i;
                ur[i] = up[(size_t)((tn < T_) ? tn : 0) * H_];

                u64 a0 = 0, a1 = 0, a2 = 0, a3 = 0;
#pragma unroll
                for (int k = 0; k < 16; k += 4) {
                    a0 = fma2(We[k],     he[k],     a0);
                    a1 = fma2(We[k + 1], he[k + 1], a1);
                    a2 = fma2(We[k + 2], he[k + 2], a2);
                    a3 = fma2(We[k + 3], he[k + 3], a3);
                }
                const float hE = tanh_fast(u + hsum4(a0, a1, a2, a3));

                she[lane] = hE;
                FENCE();
                {
                    const ulonglong2* q = reinterpret_cast<const ulonglong2*>(she);
#pragma unroll
                    for (int k = 0; k < 8; k++) {
                        ulonglong2 v = q[k];
                        he[2 * k]     = v.x;
                        he[2 * k + 1] = v.y;
                    }
                }
                FENCE();
                u64 m0 = 0, m1 = 0, m2 = 0, m3 = 0;
#pragma unroll
                for (int k = 0; k < 16; k += 4) {
                    m0 = fma2(Mm[k],     he[k],     m0);
                    m1 = fma2(Mm[k + 1], he[k + 1], m1);
                    m2 = fma2(Mm[k + 2], he[k + 2], m2);
                    m3 = fma2(Mm[k + 3], he[k + 3], m3);
                }
                ring[(t + i) & (RINGD - 1)][lane] = hsum4(m0, m1, m2, m3);
            }
            __syncwarp();
            *(volatile int*)&enc_flag = t + 4;   // all lanes store same value
        }
    } else {
        // ---------------- consumer: decoder recurrence ---------------------
        u64 Wd[16];
        {
            const u64* d = reinterpret_cast<const u64*>(Wdec_g + lane * H_);
#pragma unroll
            for (int k = 0; k < 16; k++) Wd[k] = d[k];
        }
        float btot = bco[lane] + bresd[lane];
#pragma unroll
        for (int c = 0; c < C_; c++) btot = fmaf(Wco[lane * C_ + c], bcode[c], btot);

        u64 hd[16];
#pragma unroll
        for (int k = 0; k < 16; k++) hd[k] = 0ull;

        float* dp = g_dec + ((size_t)b * T_) * H_ + lane;

        for (int t = 0; t < T_; t += 4) {
            while (*(volatile int*)&enc_flag < t + 4) {}
            FENCE();
#pragma unroll
            for (int i = 0; i < 4; i++) {
                const float v = ring[(t + i) & (RINGD - 1)][lane];

                u64 d0 = 0, d1 = 0, d2 = 0, d3 = 0;
#pragma unroll
                for (int k = 0; k < 16; k += 4) {
                    d0 = fma2(Wd[k],     hd[k],     d0);
                    d1 = fma2(Wd[k + 1], hd[k + 1], d1);
                    d2 = fma2(Wd[k + 2], hd[k + 2], d2);
                    d3 = fma2(Wd[k + 3], hd[k + 3], d3);
                }
                const float hD = tanh_fast(v + btot + hsum4(d0, d1, d2, d3));

                shd[lane] = hD;
                FENCE();
                dp[(size_t)(t + i) * H_] = hD;
                {
                    const ulonglong2* q = reinterpret_cast<const ulonglong2*>(shd);
#pragma unroll
                    for (int k = 0; k < 8; k++) {
                        ulonglong2 v2 = q[k];
                        hd[2 * k]     = v2.x;
                        hd[2 * k + 1] = v2.y;
                    }
                }
                FENCE();
            }
            __syncwarp();
            *(volatile int*)&dec_flag = t + 4;
        }
    }
}

// ---------------- Kernel 3: out = dec @ W_ro^T + b_ro ----------------
// No smem. lane computes h = {2*lane, 2*lane+1}; g_dec row broadcast via
// uniform LDG.128; packed STG.64 output. 4 rows/iter.
#define K3_GRID 304
__global__ void __launch_bounds__(128) k_proj_out(const float* __restrict__ Wro,
                                                  const float* __restrict__ bro,
                                                  float* __restrict__ out) {
    const int lane = threadIdx.x & 31;
    const int gw   = (blockIdx.x * blockDim.x + threadIdx.x) >> 5;
    const int nw   = (K3_GRID * 128) >> 5;

    u64 W0[16], W1[16];
    {
        const u64* r0 = reinterpret_cast<const u64*>(Wro + (2 * lane) * H_);
        const u64* r1 = reinterpret_cast<const u64*>(Wro + (2 * lane + 1) * H_);
#pragma unroll
        for (int k = 0; k < 16; k++) { W0[k] = r0[k]; W1[k] = r1[k]; }
    }
    const float c0 = bro[2 * lane];
    const float c1 = bro[2 * lane + 1];

    const ulonglong2* d2 = reinterpret_cast<const ulonglong2*>(g_dec);
    u64* o64 = reinterpret_cast<u64*>(out);

    for (size_t r = (size_t)gw * 4; r < R_; r += (size_t)nw * 4) {
        ulonglong2 X[4][8];
#pragma unroll
        for (int j = 0; j < 4; j++) {
            const ulonglong2* p = d2 + (r + j) * (H_ / 4);
#pragma unroll
            for (int k = 0; k < 8; k++) X[j][k] = __ldg(p + k);
        }
#pragma unroll
        for (int j = 0; j < 4; j++) {
            u64 a0 = 0, a1 = 0, b0 = 0, b1 = 0;
#pragma unroll
            for (int k = 0; k < 8; k++) {
                a0 = fma2(W0[2 * k],     X[j][k].x, a0);
                a1 = fma2(W0[2 * k + 1], X[j][k].y, a1);
                b0 = fma2(W1[2 * k],     X[j][k].x, b0);
                b1 = fma2(W1[2 * k + 1], X[j][k].y, b1);
            }
            o64[(r + j) * (DIN / 2) + lane] =
                pack2(c0 + unpack_sum(add2(a0, a1)),
                      c1 + unpack_sum(add2(b0, b1)));
        }
    }
}

// ---------------- launch ----------------
extern "C" void kernel_launch(void* const* d_in, const int* in_sizes, int n_in,
                              void* d_out, int out_size) {
    const float* x     = (const float*)d_in[0];
    const float* Win   = (const float*)d_in[1];
    const float* bin   = (const float*)d_in[2];
    const float* Wrese = (const float*)d_in[3];
    const float* brese = (const float*)d_in[4];
    const float* Wcode = (const float*)d_in[5];
    const float* bcode = (const float*)d_in[6];
    const float* Wco   = (const float*)d_in[7];
    const float* bco   = (const float*)d_in[8];
    const float* Wresd = (const float*)d_in[9];
    const float* bresd = (const float*)d_in[10];
    const float* Wro   = (const float*)d_in[11];
    const float* bro   = (const float*)d_in[12];
    float* out = (float*)d_out;

    k_proj_in<<<K1_GRID, 128>>>(x, Win, bin, brese);
    k_scan<<<B_, 64>>>(Wrese, Wresd, Wcode, bcode, Wco, bco, bresd);
    k_proj_out<<<K3_GRID, 128>>>(Wro, bro, out);
}

// round 6
// speedup vs baseline: 2.6441x; 2.6441x over previous
#include <cuda_runtime.h>

typedef unsigned long long u64;

#define B_   256
#define T_   2048
#define DIN  64
#define H_   32
#define C_   16
#define R_   (B_ * T_)

// Scratch (allocation-free rule: __device__ global)
__device__ float g_u[(size_t)R_ * H_];    // x@W_in^T + b_in + b_res_enc

#define FENCE() asm volatile("" ::: "memory")

// ---------------- packed f32x2 helpers (Blackwell FFMA2) ----------------
__device__ __forceinline__ u64 fma2(u64 a, u64 b, u64 c) {
    u64 d;
    asm("fma.rn.f32x2 %0, %1, %2, %3;" : "=l"(d) : "l"(a), "l"(b), "l"(c));
    return d;
}
__device__ __forceinline__ u64 add2(u64 a, u64 b) {
    u64 d;
    asm("add.rn.f32x2 %0, %1, %2;" : "=l"(d) : "l"(a), "l"(b));
    return d;
}
__device__ __forceinline__ u64 pack2(float lo, float hi) {
    u64 r;
    asm("mov.b64 %0, {%1, %2};" : "=l"(r) : "f"(lo), "f"(hi));
    return r;
}
__device__ __forceinline__ float unpack_sum(u64 v) {
    float lo, hi;
    asm("mov.b64 {%0, %1}, %2;" : "=f"(lo), "=f"(hi) : "l"(v));
    return lo + hi;
}
__device__ __forceinline__ float hsum4(u64 a0, u64 a1, u64 a2, u64 a3) {
    return unpack_sum(add2(add2(a0, a1), add2(a2, a3)));
}
// tanh = 1 - 2/(1+e^{2x}); e^{2x}: 0 -> -1, inf -> +1, no NaN path, no clamps
__device__ __forceinline__ float tanh_fast(float x) {
    float e = __expf(2.0f * x);
    return 1.0f - __fdividef(2.0f, 1.0f + e);
}

// ---------------- Kernel 1: u = x @ W_in^T + (b_in + b_res_enc) ----------------
// Sliced broadcast: warp = 4 groups x 8 lanes. Tile = 16 rows (group g owns
// rows 4m+g, m=0..3). lane (g,s) computes h = s+8j, j=0..3 for its rows.
// x rows padded to 17 float4 (68 floats) -> per-instr 4 distinct 16B chunks,
// conflict-free (bank shift 4 per row). W padded the same; 8 distinct rows
// per W-LDS, banks 4s+4k, conflict-free. 8 LDS.128/row vs 64 in R4.
#define K1_GRID 296
#define K1_NT   (R_ / 16)     // 32768 tiles
__global__ void __launch_bounds__(256) k_proj_in(const float* __restrict__ x,
                                                 const float* __restrict__ Win,
                                                 const float* __restrict__ bin,
                                                 const float* __restrict__ brese) {
    __shared__ __align__(16) float4 ws[32 * 17];        // W_in padded
    __shared__ __align__(16) float4 xs[8][16 * 17];     // per-warp x tiles
    const int tid  = threadIdx.x;
    const int lane = tid & 31;
    const int w    = tid >> 5;
    const int s    = lane & 7;
    const int g    = lane >> 3;

    // stage W_in (32x64 -> padded stride 17 f4)
    for (int i = tid; i < 512; i += 256) {
        ws[(i >> 4) * 17 + (i & 15)] = reinterpret_cast<const float4*>(Win)[i];
    }
    __syncthreads();

    float bias[4];
#pragma unroll
    for (int j = 0; j < 4; j++) bias[j] = bin[s + 8 * j] + brese[s + 8 * j];

    const float4* x4 = reinterpret_cast<const float4*>(x);
    const int nwarp = K1_GRID * 8;
    int tile = blockIdx.x * 8 + w;

    float4 cur[8];
    if (tile < K1_NT) {
        const float4* src = x4 + (size_t)tile * 256;
#pragma unroll
        for (int i = 0; i < 8; i++) cur[i] = src[lane + i * 32];
    }

    while (tile < K1_NT) {
        // stage current tile (pad to stride 17)
#pragma unroll
        for (int i = 0; i < 8; i++) {
            const int idx = lane + i * 32;
            xs[w][(idx >> 4) * 17 + (idx & 15)] = cur[i];
        }
        __syncwarp();

        const int nt = tile + nwarp;
        if (nt < K1_NT) {
            const float4* src = x4 + (size_t)nt * 256;
#pragma unroll
            for (int i = 0; i < 8; i++) cur[i] = src[lane + i * 32];
        }

        u64 acc[4][4];
#pragma unroll
        for (int m = 0; m < 4; m++)
#pragma unroll
            for (int j = 0; j < 4; j++) acc[m][j] = 0ull;

        const float4* xw = xs[w];
#pragma unroll
        for (int k = 0; k < 16; k++) {
            ulonglong2 xk[4], wk[4];
#pragma unroll
            for (int m = 0; m < 4; m++)
                xk[m] = *reinterpret_cast<const ulonglong2*>(&xw[(4 * m + g) * 17 + k]);
#pragma unroll
            for (int j = 0; j < 4; j++)
                wk[j] = *reinterpret_cast<const ulonglong2*>(&ws[(s + 8 * j) * 17 + k]);
#pragma unroll
            for (int m = 0; m < 4; m++)
#pragma unroll
                for (int j = 0; j < 4; j++) {
                    acc[m][j] = fma2(wk[j].x, xk[m].x, acc[m][j]);
                    acc[m][j] = fma2(wk[j].y, xk[m].y, acc[m][j]);
                }
        }

        const size_t rbase = (size_t)tile * 16;
#pragma unroll
        for (int m = 0; m < 4; m++) {
            float* urow = g_u + (rbase + 4 * m + g) * H_;
#pragma unroll
            for (int j = 0; j < 4; j++)
                urow[s + 8 * j] = bias[j] + unpack_sum(acc[m][j]);
        }
        __syncwarp();   // all lanes done reading xs[w] before next STS
        tile = nt;
    }
}

// ---------------- Kernel 2: 3-warp pipelined dual ESN scan + fused readout --
// warp0 (producer): h_enc recurrence, v = (W_co@W_code) h_enc  -> ring_v
// warp1 (consumer): h_dec = tanh(v + W_dec h_dec + btot)       -> ring_d
// warp2 (readout):  out = W_ro h_dec + b_ro                    -> d_out
// Flags: enc_flag >= dec_flag >= ro_flag; ring reuse guarded by ro_flag.
#define RINGD 32
__global__ void __launch_bounds__(96) k_scan(const float* __restrict__ Wenc_g,
                                             const float* __restrict__ Wdec_g,
                                             const float* __restrict__ Wcode,
                                             const float* __restrict__ bcode,
                                             const float* __restrict__ Wco,
                                             const float* __restrict__ bco,
                                             const float* __restrict__ bresd,
                                             const float* __restrict__ Wro,
                                             const float* __restrict__ bro,
                                             float* __restrict__ out) {
    const int lane = threadIdx.x & 31;
    const int wid  = threadIdx.x >> 5;
    const int b    = blockIdx.x;
    __shared__ __align__(16) float ring_v[RINGD][H_];
    __shared__ __align__(16) float ring_d[RINGD][H_];
    __shared__ __align__(16) float she[H_];
    __shared__ int enc_flag;
    __shared__ int dec_flag;
    __shared__ int ro_flag;

    if (threadIdx.x == 0) { enc_flag = 0; dec_flag = 0; ro_flag = 0; }
    __syncthreads();

    if (wid == 0) {
        // ---------------- producer: encoder + fused code->co projection ----
        u64 We[16], Mm[16];
        {
            const u64* a = reinterpret_cast<const u64*>(Wenc_g + lane * H_);
#pragma unroll
            for (int k = 0; k < 16; k++) We[k] = a[k];
        }
        {
            float wc[C_];
#pragma unroll
            for (int c = 0; c < C_; c++) wc[c] = Wco[lane * C_ + c];
#pragma unroll
            for (int k = 0; k < 16; k++) {
                u64 m = 0;
#pragma unroll
                for (int c = 0; c < C_; c++) {
                    m = fma2(pack2(wc[c], wc[c]),
                             reinterpret_cast<const u64*>(Wcode + c * H_)[k], m);
                }
                Mm[k] = m;
            }
        }
        u64 he[16];
#pragma unroll
        for (int k = 0; k < 16; k++) he[k] = 0ull;

        const float* up = g_u + ((size_t)b * T_) * H_ + lane;
        float ur[4];
#pragma unroll
        for (int i = 0; i < 4; i++) ur[i] = up[(size_t)i * H_];

        for (int t = 0; t < T_; t += 4) {
            // ro_flag is the global minimum: guards ring_v and ring_d reuse
            while (t - *(volatile int*)&ro_flag > RINGD - 8) {}
#pragma unroll
            for (int i = 0; i < 4; i++) {
                const float u = ur[i];
                const int tn  = t + 4 + i;
                ur[i] = up[(size_t)((tn < T_) ? tn : 0) * H_];

                u64 a0 = 0, a1 = 0, a2 = 0, a3 = 0;
#pragma unroll
                for (int k = 0; k < 16; k += 4) {
                    a0 = fma2(We[k],     he[k],     a0);
                    a1 = fma2(We[k + 1], he[k + 1], a1);
                    a2 = fma2(We[k + 2], he[k + 2], a2);
                    a3 = fma2(We[k + 3], he[k + 3], a3);
                }
                const float hE = tanh_fast(u + hsum4(a0, a1, a2, a3));

                she[lane] = hE;
                FENCE();
                {
                    const ulonglong2* q = reinterpret_cast<const ulonglong2*>(she);
#pragma unroll
                    for (int k = 0; k < 8; k++) {
                        ulonglong2 v = q[k];
                        he[2 * k]     = v.x;
                        he[2 * k + 1] = v.y;
                    }
                }
                FENCE();
                u64 m0 = 0, m1 = 0, m2 = 0, m3 = 0;
#pragma unroll
                for (int k = 0; k < 16; k += 4) {
                    m0 = fma2(Mm[k],     he[k],     m0);
                    m1 = fma2(Mm[k + 1], he[k + 1], m1);
                    m2 = fma2(Mm[k + 2], he[k + 2], m2);
                    m3 = fma2(Mm[k + 3], he[k + 3], m3);
                }
                ring_v[(t + i) & (RINGD - 1)][lane] = hsum4(m0, m1, m2, m3);
            }
            __syncwarp();
            *(volatile int*)&enc_flag = t + 4;
        }
    } else if (wid == 1) {
        // ---------------- consumer: decoder recurrence ---------------------
        u64 Wd[16];
        {
            const u64* d = reinterpret_cast<const u64*>(Wdec_g + lane * H_);
#pragma unroll
            for (int k = 0; k < 16; k++) Wd[k] = d[k];
        }
        float btot = bco[lane] + bresd[lane];
#pragma unroll
        for (int c = 0; c < C_; c++) btot = fmaf(Wco[lane * C_ + c], bcode[c], btot);

        u64 hd[16];
#pragma unroll
        for (int k = 0; k < 16; k++) hd[k] = 0ull;

        for (int t = 0; t < T_; t += 4) {
            while (*(volatile int*)&enc_flag < t + 4) {}
            while (t - *(volatile int*)&ro_flag > RINGD - 8) {}   // ring_d reuse
            FENCE();
#pragma unroll
            for (int i = 0; i < 4; i++) {
                const float v = ring_v[(t + i) & (RINGD - 1)][lane];

                u64 d0 = 0, d1 = 0, d2 = 0, d3 = 0;
#pragma unroll
                for (int k = 0; k < 16; k += 4) {
                    d0 = fma2(Wd[k],     hd[k],     d0);
                    d1 = fma2(Wd[k + 1], hd[k + 1], d1);
                    d2 = fma2(Wd[k + 2], hd[k + 2], d2);
                    d3 = fma2(Wd[k + 3], hd[k + 3], d3);
                }
                const float hD = tanh_fast(v + btot + hsum4(d0, d1, d2, d3));

                ring_d[(t + i) & (RINGD - 1)][lane] = hD;
                FENCE();
                {
                    const ulonglong2* q =
                        reinterpret_cast<const ulonglong2*>(ring_d[(t + i) & (RINGD - 1)]);
#pragma unroll
                    for (int k = 0; k < 8; k++) {
                        ulonglong2 v2 = q[k];
                        hd[2 * k]     = v2.x;
                        hd[2 * k + 1] = v2.y;
                    }
                }
                FENCE();
            }
            __syncwarp();
            *(volatile int*)&dec_flag = t + 4;
        }
    } else {
        // ---------------- readout: out = W_ro h_dec + b_ro -----------------
        u64 W0[16], W1[16];   // rows 2*lane, 2*lane+1 of Wro [64][32]
        {
            const u64* r0 = reinterpret_cast<const u64*>(Wro + (2 * lane) * H_);
            const u64* r1 = reinterpret_cast<const u64*>(Wro + (2 * lane + 1) * H_);
#pragma unroll
            for (int k = 0; k < 16; k++) { W0[k] = r0[k]; W1[k] = r1[k]; }
        }
        const float c0 = bro[2 * lane];
        const float c1 = bro[2 * lane + 1];

        u64* o64 = reinterpret_cast<u64*>(out) + (size_t)b * T_ * (DIN / 2) + lane;

        for (int t = 0; t < T_; t += 4) {
            while (*(volatile int*)&dec_flag < t + 4) {}
            FENCE();
#pragma unroll
            for (int i = 0; i < 4; i++) {
                u64 hv[16];
                {
                    const ulonglong2* q =
                        reinterpret_cast<const ulonglong2*>(ring_d[(t + i) & (RINGD - 1)]);
#pragma unroll
                    for (int k = 0; k < 8; k++) {
                        ulonglong2 v = q[k];
                        hv[2 * k]     = v.x;
                        hv[2 * k + 1] = v.y;
                    }
                }
                u64 a0 = 0, a1 = 0, b0 = 0, b1 = 0;
#pragma unroll
                for (int k = 0; k < 8; k++) {
                    a0 = fma2(W0[2 * k],     hv[2 * k],     a0);
                    a1 = fma2(W0[2 * k + 1], hv[2 * k + 1], a1);
                    b0 = fma2(W1[2 * k],     hv[2 * k],     b0);
                    b1 = fma2(W1[2 * k + 1], hv[2 * k + 1], b1);
                }
                o64[(size_t)(t + i) * (DIN / 2)] =
                    pack2(c0 + unpack_sum(add2(a0, a1)),
                          c1 + unpack_sum(add2(b0, b1)));
            }
            FENCE();
            __syncwarp();
            *(volatile int*)&ro_flag = t + 4;
        }
    }
}

// ---------------- launch ----------------
extern "C" void kernel_launch(void* const* d_in, const int* in_sizes, int n_in,
                              void* d_out, int out_size) {
    const float* x     = (const float*)d_in[0];
    const float* Win   = (const float*)d_in[1];
    const float* bin   = (const float*)d_in[2];
    const float* Wrese = (const float*)d_in[3];
    const float* brese = (const float*)d_in[4];
    const float* Wcode = (const float*)d_in[5];
    const float* bcode = (const float*)d_in[6];
    const float* Wco   = (const float*)d_in[7];
    const float* bco   = (const float*)d_in[8];
    const float* Wresd = (const float*)d_in[9];
    const float* bresd = (const float*)d_in[10];
    const float* Wro   = (const float*)d_in[11];
    const float* bro   = (const float*)d_in[12];
    float* out = (float*)d_out;

    k_proj_in<<<K1_GRID, 256>>>(x, Win, bin, brese);
    k_scan<<<B_, 96>>>(Wrese, Wresd, Wcode, bcode, Wco, bco, bresd, Wro, bro, out);
}